// round 13
// baseline (speedup 1.0000x reference)
#include <cuda_runtime.h>

// GraphAttentionHeadModule: N=8192, IN_F=256, OUT_F=64, alpha=0.2
// out = elu( softmax(mask(leaky_relu(s1 + s2^T))) @ (X@W) )
//
// Inputs (metadata order):
//  d_in[0] node_features f32 [8192,256]
//  d_in[1] adj_matrix    i32 [8192,8192]
//  d_in[2] W             f32 [256,64]
//  d_in[3] a_1           f32 [64,1]
//  d_in[4] a_2           f32 [64,1]
// Output f32 [8192,64]

#define GN 8192
#define GIN 256
#define GOUT 64
#define CAPV 20.0f

// scratch (no allocations allowed)
__device__ float g_h[GN * GOUT];   // h_prime, 2 MB
__device__ float g_s1[GN];
__device__ float g_s2[GN];

// ---------------------------------------------------------------------------
// Kernel 1: h = X @ W.  grid 256, block 256. Each block: 32 rows.
// Thread: c = t&63 (output channel), rg = t>>6 (row group of 8).
// ---------------------------------------------------------------------------
__global__ void __launch_bounds__(256) gat_hprime_kernel(
    const float* __restrict__ X, const float* __restrict__ W)
{
    const int t = threadIdx.x;
    const int c = t & 63;
    const int rg = t >> 6;           // 0..3
    const int r0 = blockIdx.x * 32 + rg * 8;

    float acc[8];
#pragma unroll
    for (int i = 0; i < 8; ++i) acc[i] = 0.f;

#pragma unroll 4
    for (int k = 0; k < GIN; k += 4) {
        const float w0 = W[(k + 0) * GOUT + c];
        const float w1 = W[(k + 1) * GOUT + c];
        const float w2 = W[(k + 2) * GOUT + c];
        const float w3 = W[(k + 3) * GOUT + c];
#pragma unroll
        for (int rr = 0; rr < 8; ++rr) {
            const float4 xv = *(const float4*)(X + (size_t)(r0 + rr) * GIN + k);
            acc[rr] += xv.x * w0 + xv.y * w1 + xv.z * w2 + xv.w * w3;
        }
    }
#pragma unroll
    for (int rr = 0; rr < 8; ++rr)
        g_h[(size_t)(r0 + rr) * GOUT + c] = acc[rr];
}

// ---------------------------------------------------------------------------
// Kernel 2: s1 = h @ a1, s2 = h @ a2.  warp per row (strided).
// grid 256, block 256 -> 2048 warps, 4 rows each.
// ---------------------------------------------------------------------------
__global__ void __launch_bounds__(256) gat_scores_kernel(
    const float* __restrict__ a1, const float* __restrict__ a2)
{
    const int lane = threadIdx.x & 31;
    const int gwid = (blockIdx.x * blockDim.x + threadIdx.x) >> 5;  // 0..2047

    const float2 a1v = *(const float2*)(a1 + lane * 2);
    const float2 a2v = *(const float2*)(a2 + lane * 2);

    for (int r = gwid; r < GN; r += 2048) {
        const float2 hv = *(const float2*)(g_h + (size_t)r * GOUT + lane * 2);
        float p1 = hv.x * a1v.x + hv.y * a1v.y;
        float p2 = hv.x * a2v.x + hv.y * a2v.y;
#pragma unroll
        for (int off = 16; off > 0; off >>= 1) {
            p1 += __shfl_xor_sync(0xffffffffu, p1, off);
            p2 += __shfl_xor_sync(0xffffffffu, p2, off);
        }
        if (lane == 0) { g_s1[r] = p1; g_s2[r] = p2; }
    }
}

// ---------------------------------------------------------------------------
// Kernel 3: fused masked-softmax weighted sum + ELU.
// grid 256 blocks (32 rows each), block 256 threads, 2 blocks/SM -> 1 wave.
// Per tile of 128 j:
//   phase 1: thread (r=lane, q=wid) computes w = adj ? exp(lrelu(s1_r+s2_j)-20) : 0
//            stored duplicated as float2(w,w) in smem for packed FMA.
//   phase 2: warp wid handles 16 j; lane owns channels (2*lane, 2*lane+1),
//            acc[r] += {w_r,w_r} * {h_j[2l], h_j[2l+1]} via fma.rn.f32x2.
// Epilogue: deterministic cross-warp reduction, divide by row denom, ELU.
// ---------------------------------------------------------------------------
__device__ __forceinline__ void fma2(unsigned long long& a,
                                     unsigned long long b,
                                     unsigned long long c)
{
    asm("fma.rn.f32x2 %0, %1, %2, %0;" : "+l"(a) : "l"(b), "l"(c));
}

__global__ void __launch_bounds__(256, 2) gat_attn_kernel(
    const int* __restrict__ adj, float* __restrict__ out)
{
    __shared__ float s1s[32];
    __shared__ float denomS[32];
    __shared__ float dred[256];
    __shared__ __align__(16) float2 wbuf[128 * 32];   // 32 KB: wbuf[jl][r]

    const int t    = threadIdx.x;
    const int lane = t & 31;
    const int wid  = t >> 5;
    const int row0 = blockIdx.x * 32;

    if (t < 32) s1s[t] = g_s1[row0 + t];
    __syncthreads();

    const float s1r = s1s[lane];                            // phase-1 row = lane
    const int* adjrow = adj + (size_t)(row0 + lane) * GN;

    unsigned long long acc[32];
#pragma unroll
    for (int i = 0; i < 32; ++i) acc[i] = 0ULL;
    float dn = 0.f;

    for (int tile = 0; tile < GN; tile += 128) {
        // ---- phase 1: compute w tile ----
#pragma unroll
        for (int step = 0; step < 4; ++step) {
            const int jl = step * 32 + wid * 4;
            const int j  = tile + jl;
            const int4  a4  = *(const int4*)(adjrow + j);
            const float4 s2v = *(const float4*)(g_s2 + j);

            float e, l, w0, w1, w2, w3;
            e = s1r + s2v.x; l = fmaxf(e, 0.2f * e) - CAPV;
            w0 = (a4.x > 0) ? __expf(l) : 0.f;
            e = s1r + s2v.y; l = fmaxf(e, 0.2f * e) - CAPV;
            w1 = (a4.y > 0) ? __expf(l) : 0.f;
            e = s1r + s2v.z; l = fmaxf(e, 0.2f * e) - CAPV;
            w2 = (a4.z > 0) ? __expf(l) : 0.f;
            e = s1r + s2v.w; l = fmaxf(e, 0.2f * e) - CAPV;
            w3 = (a4.w > 0) ? __expf(l) : 0.f;

            dn += (w0 + w1) + (w2 + w3);
            wbuf[(jl + 0) * 32 + lane] = make_float2(w0, w0);
            wbuf[(jl + 1) * 32 + lane] = make_float2(w1, w1);
            wbuf[(jl + 2) * 32 + lane] = make_float2(w2, w2);
            wbuf[(jl + 3) * 32 + lane] = make_float2(w3, w3);
        }
        __syncthreads();

        // ---- phase 2: accumulate ----
        const int jl0 = wid * 16;
        unsigned long long hv =
            *(const unsigned long long*)(g_h + (((size_t)(tile + jl0)) << 6) + (lane << 1));
#pragma unroll 1
        for (int k = 0; k < 16; ++k) {
            const unsigned long long hcur = hv;
            if (k < 15)
                hv = *(const unsigned long long*)(g_h +
                        (((size_t)(tile + jl0 + k + 1)) << 6) + (lane << 1));
            const ulonglong2* wp = (const ulonglong2*)(wbuf + (jl0 + k) * 32);
#pragma unroll
            for (int i = 0; i < 16; ++i) {
                const ulonglong2 ww = wp[i];       // rows 2i, 2i+1 (duplicated w)
                fma2(acc[2 * i],     ww.x, hcur);
                fma2(acc[2 * i + 1], ww.y, hcur);
            }
        }
        __syncthreads();
    }

    // ---- denominator reduction (deterministic) ----
    dred[t] = dn;
    __syncthreads();
    if (t < 32) {
        float s = 0.f;
#pragma unroll
        for (int q = 0; q < 8; ++q) s += dred[q * 32 + t];
        denomS[t] = s;
    }

    // ---- output reduction: 4 chunks of 8 rows, reuse wbuf as staging ----
    float* red = (float*)wbuf;   // 8 rows * 64 ch * 8 warps * 4B = 16 KB
#pragma unroll 1
    for (int chunk = 0; chunk < 4; ++chunk) {
        __syncthreads();
#pragma unroll
        for (int rr = 0; rr < 8; ++rr) {
            const unsigned long long v = acc[chunk * 8 + rr];
            const float lo = __uint_as_float((unsigned)(v & 0xffffffffu));
            const float hi = __uint_as_float((unsigned)(v >> 32));
            red[(rr * 64 + 2 * lane)     * 8 + wid] = lo;
            red[(rr * 64 + 2 * lane + 1) * 8 + wid] = hi;
        }
        __syncthreads();
#pragma unroll
        for (int s = 0; s < 2; ++s) {
            const int idx = s * 256 + t;           // 0..511
            const int rr = idx >> 6;
            const int c  = idx & 63;
            const int r  = chunk * 8 + rr;
            float v = 0.f;
#pragma unroll
            for (int q = 0; q < 8; ++q) v += red[(rr * 64 + c) * 8 + q];
            v = v / denomS[r];
            v = (v > 0.f) ? v : expm1f(v);         // ELU
            out[(size_t)(row0 + r) * GOUT + c] = v;
        }
    }
}

// ---------------------------------------------------------------------------
extern "C" void kernel_launch(void* const* d_in, const int* in_sizes, int n_in,
                              void* d_out, int out_size)
{
    const float* X   = (const float*)d_in[0];
    const int*   adj = (const int*)d_in[1];
    const float* W   = (const float*)d_in[2];
    const float* a1  = (const float*)d_in[3];
    const float* a2  = (const float*)d_in[4];
    float* out = (float*)d_out;

    gat_hprime_kernel<<<256, 256>>>(X, W);
    gat_scores_kernel<<<256, 256>>>(a1, a2);
    gat_attn_kernel<<<256, 256>>>(adj, out);
}